// round 1
// baseline (speedup 1.0000x reference)
#include <cuda_runtime.h>
#include <cstdint>

// Problem constants
#define D_MODEL 512
#define NHEAD   8
#define DK      64
#define BATCH   8192
#define SEQ     14
#define MROWS   (BATCH*SEQ)   // 114688

// Scratch (static device globals — allocation-free per harness rules)
__device__ float g_QKV[(size_t)MROWS * 1536];   // [M][1536]: Q | K | V
__device__ float g_attn[(size_t)MROWS * 512];   // attention output, head-concat layout

// ---------------------------------------------------------------------------
// tf32 helpers
// ---------------------------------------------------------------------------
__device__ __forceinline__ float to_tf32(float x) {
    uint32_t u;
    asm("cvt.rna.tf32.f32 %0, %1;" : "=r"(u) : "f"(x));
    return __uint_as_float(u);
}

__device__ __forceinline__ void mma_tf32(float c[4], const uint32_t a[4], const uint32_t b[2]) {
    asm volatile(
        "mma.sync.aligned.m16n8k8.row.col.f32.tf32.tf32.f32 "
        "{%0,%1,%2,%3}, {%4,%5,%6,%7}, {%8,%9}, {%0,%1,%2,%3};\n"
        : "+f"(c[0]), "+f"(c[1]), "+f"(c[2]), "+f"(c[3])
        : "r"(a[0]), "r"(a[1]), "r"(a[2]), "r"(a[3]), "r"(b[0]), "r"(b[1]));
}

// ---------------------------------------------------------------------------
// Generic GEMM: out[r][bx*128 + c] = sum_k X[r,k] * W[(bx&3)*128 + c, k] + bias
// W selected per 512-wide matrix: mat = bx>>2 -> (W0,B0)/(W1,B1)/(W2,B2).
// X is [M, 512] row-major, W is [512, 512] row-major ("row.col" mma: W rows
// are contiguous over k, which is exactly col-major B).
// ---------------------------------------------------------------------------
#define BM 128
#define BN 128
#define BKT 32
#define LDS_K 36   // BKT + 4 pad: bank = (4*r + k) % 32 -> conflict-free frags

__global__ __launch_bounds__(256, 2)
void gemm_tf32(const float* __restrict__ X,
               const float* __restrict__ W0, const float* __restrict__ W1, const float* __restrict__ W2,
               const float* __restrict__ B0, const float* __restrict__ B1, const float* __restrict__ B2,
               float* __restrict__ out, int ldo)
{
    __shared__ float As[BM][LDS_K];
    __shared__ float Bs[BN][LDS_K];

    const int tid  = threadIdx.x;
    const int lane = tid & 31;
    const int wid  = tid >> 5;
    const int wm   = wid >> 1;      // 0..3 -> 32-row strip
    const int wn   = wid & 1;       // 0..1 -> 64-col strip
    const int gid  = lane >> 2;     // 0..7
    const int tig  = lane & 3;      // 0..3

    const int bx = blockIdx.x, by = blockIdx.y;
    const int mat = bx >> 2;
    const float* W  = (mat == 0) ? W0 : (mat == 1) ? W1 : W2;
    const float* Bb = (mat == 0) ? B0 : (mat == 1) ? B1 : B2;
    const int  wrow0 = (bx & 3) * BN;      // row base inside the 512x512 W
    const long row0  = (long)by * BM;      // row base of X / out

    float acc[2][8][4];
    #pragma unroll
    for (int i = 0; i < 2; i++)
        #pragma unroll
        for (int j = 0; j < 8; j++)
            #pragma unroll
            for (int k = 0; k < 4; k++) acc[i][j][k] = 0.f;

    for (int kb = 0; kb < D_MODEL; kb += BKT) {
        __syncthreads();
        #pragma unroll
        for (int t = 0; t < 4; t++) {
            int idx = tid + t * 256;        // 0..1023
            int r   = idx >> 3;             // 0..127
            int kq  = (idx & 7) << 2;       // 0..28 step 4
            float4 av = *(const float4*)&X[(row0 + r) * D_MODEL + kb + kq];
            As[r][kq + 0] = to_tf32(av.x);
            As[r][kq + 1] = to_tf32(av.y);
            As[r][kq + 2] = to_tf32(av.z);
            As[r][kq + 3] = to_tf32(av.w);
            float4 bv = *(const float4*)&W[(long)(wrow0 + r) * D_MODEL + kb + kq];
            Bs[r][kq + 0] = to_tf32(bv.x);
            Bs[r][kq + 1] = to_tf32(bv.y);
            Bs[r][kq + 2] = to_tf32(bv.z);
            Bs[r][kq + 3] = to_tf32(bv.w);
        }
        __syncthreads();

        #pragma unroll
        for (int kk = 0; kk < BKT; kk += 8) {
            uint32_t a[2][4], b[8][2];
            #pragma unroll
            for (int mt = 0; mt < 2; mt++) {
                int m = wm * 32 + mt * 16 + gid;
                a[mt][0] = __float_as_uint(As[m    ][kk + tig    ]);
                a[mt][1] = __float_as_uint(As[m + 8][kk + tig    ]);
                a[mt][2] = __float_as_uint(As[m    ][kk + tig + 4]);
                a[mt][3] = __float_as_uint(As[m + 8][kk + tig + 4]);
            }
            #pragma unroll
            for (int nt = 0; nt < 8; nt++) {
                int n = wn * 64 + nt * 8 + gid;
                b[nt][0] = __float_as_uint(Bs[n][kk + tig    ]);
                b[nt][1] = __float_as_uint(Bs[n][kk + tig + 4]);
            }
            #pragma unroll
            for (int mt = 0; mt < 2; mt++)
                #pragma unroll
                for (int nt = 0; nt < 8; nt++)
                    mma_tf32(acc[mt][nt], a[mt], b[nt]);
        }
    }

    // Epilogue: add bias, write float2 pairs
    #pragma unroll
    for (int mt = 0; mt < 2; mt++) {
        long r0 = row0 + wm * 32 + mt * 16 + gid;
        #pragma unroll
        for (int nt = 0; nt < 8; nt++) {
            int cl = wn * 64 + nt * 8 + tig * 2;      // col inside 128-tile
            int cW = wrow0 + cl;                      // bias index (within matrix)
            long cO = (long)bx * BN + cl;             // global out col
            float2 bb = *(const float2*)&Bb[cW];
            float2 v0 = make_float2(acc[mt][nt][0] + bb.x, acc[mt][nt][1] + bb.y);
            float2 v1 = make_float2(acc[mt][nt][2] + bb.x, acc[mt][nt][3] + bb.y);
            *(float2*)&out[ r0      * ldo + cO] = v0;
            *(float2*)&out[(r0 + 8) * ldo + cO] = v1;
        }
    }
}

// ---------------------------------------------------------------------------
// Attention: one block per batch item, one warp per head.
// Q,K,V rows live in registers (float2 per lane = d-pair 2*lane, 2*lane+1).
// scores(n,m) = (Q[n].K[m])/8 * prior(n,m); softmax over m; out = attn @ V.
// ---------------------------------------------------------------------------
__global__ __launch_bounds__(256)
void attn_kernel(const float* __restrict__ dist,
                 const float* __restrict__ scaleP,
                 const float* __restrict__ powerP)
{
    __shared__ float sPrior[SEQ][SEQ];
    __shared__ float sS[NHEAD][SEQ][SEQ + 1];

    const int tid  = threadIdx.x;
    const int lane = tid & 31;
    const int h    = tid >> 5;
    const int b    = blockIdx.x;

    if (tid < SEQ * SEQ) {
        int n = tid / SEQ, m = tid % SEQ;
        float d  = dist[tid];
        float p  = powerP[0];
        float sc = scaleP[0];
        float dp = (d > 0.f) ? expf(p * logf(d)) : 0.f;
        sPrior[n][m] = sc / (1.f + dp) * 0.125f;   // fold in 1/sqrt(64)
    }
    __syncthreads();

    const float* base = g_QKV + (size_t)b * (SEQ * 1536);
    const int col = h * DK + 2 * lane;

    float2 q[SEQ], k[SEQ];
    #pragma unroll
    for (int m = 0; m < SEQ; m++) {
        q[m] = *(const float2*)&base[m * 1536 +        col];
        k[m] = *(const float2*)&base[m * 1536 +  512 + col];
    }

    // Phase A: scores via warp butterfly reductions
    #pragma unroll
    for (int n = 0; n < SEQ; n++) {
        float2 qn = q[n];
        #pragma unroll
        for (int m = 0; m < SEQ; m++) {
            float v = qn.x * k[m].x + qn.y * k[m].y;
            v += __shfl_xor_sync(0xffffffffu, v, 16);
            v += __shfl_xor_sync(0xffffffffu, v, 8);
            v += __shfl_xor_sync(0xffffffffu, v, 4);
            v += __shfl_xor_sync(0xffffffffu, v, 2);
            v += __shfl_xor_sync(0xffffffffu, v, 1);
            if (lane == m) sS[h][n][m] = v * sPrior[n][m];
        }
    }
    __syncwarp();

    // Phase B: softmax per (h, n) row, lanes 0..13
    if (lane < SEQ) {
        int n = lane;
        float mx = -1e30f;
        #pragma unroll
        for (int m = 0; m < SEQ; m++) mx = fmaxf(mx, sS[h][n][m]);
        float e[SEQ];
        float sum = 0.f;
        #pragma unroll
        for (int m = 0; m < SEQ; m++) { e[m] = expf(sS[h][n][m] - mx); sum += e[m]; }
        float inv = 1.f / sum;
        #pragma unroll
        for (int m = 0; m < SEQ; m++) sS[h][n][m] = e[m] * inv;
    }
    __syncwarp();

    // Phase C: out = attn @ V (attn via smem broadcast, V in regs)
    float2 v[SEQ];
    #pragma unroll
    for (int m = 0; m < SEQ; m++)
        v[m] = *(const float2*)&base[m * 1536 + 1024 + col];

    float2 acc[SEQ];
    #pragma unroll
    for (int n = 0; n < SEQ; n++) acc[n] = make_float2(0.f, 0.f);

    #pragma unroll
    for (int m = 0; m < SEQ; m++) {
        float2 vm = v[m];
        #pragma unroll
        for (int n = 0; n < SEQ; n++) {
            float a = sS[h][n][m];
            acc[n].x += a * vm.x;
            acc[n].y += a * vm.y;
        }
    }

    float* outb = g_attn + (size_t)b * (SEQ * 512);
    #pragma unroll
    for (int n = 0; n < SEQ; n++)
        *(float2*)&outb[n * 512 + col] = acc[n];
}

// ---------------------------------------------------------------------------
// Launch
// ---------------------------------------------------------------------------
extern "C" void kernel_launch(void* const* d_in, const int* in_sizes, int n_in,
                              void* d_out, int out_size)
{
    const float* x     = (const float*)d_in[0];
    const float* Wq    = (const float*)d_in[1];
    const float* bq    = (const float*)d_in[2];
    const float* Wk    = (const float*)d_in[3];
    const float* bk    = (const float*)d_in[4];
    const float* Wv    = (const float*)d_in[5];
    const float* bv    = (const float*)d_in[6];
    const float* Wo    = (const float*)d_in[7];
    const float* bo    = (const float*)d_in[8];
    const float* scale = (const float*)d_in[9];
    const float* power = (const float*)d_in[10];
    const float* dist  = (const float*)d_in[11];
    float* out = (float*)d_out;

    float* qkv = nullptr;
    float* attn = nullptr;
    cudaGetSymbolAddress((void**)&qkv,  g_QKV);
    cudaGetSymbolAddress((void**)&attn, g_attn);

    // QKV projection: [114688 x 512] x (Wq|Wk|Wv)^T + bias -> g_QKV [M x 1536]
    gemm_tf32<<<dim3(12, MROWS / BM), 256>>>(x, Wq, Wk, Wv, bq, bk, bv, qkv, 1536);

    // Attention per batch item
    attn_kernel<<<BATCH, 256>>>(dist, scale, power);

    // Output projection: g_attn x Wo^T + bo -> d_out
    gemm_tf32<<<dim3(4, MROWS / BM), 256>>>(attn, Wo, Wo, Wo, bo, bo, bo, out, 512);
}

// round 3
// speedup vs baseline: 1.1009x; 1.1009x over previous
#include <cuda_runtime.h>
#include <cuda_fp16.h>
#include <cstdint>

// ---------------------------------------------------------------------------
// Problem constants
// ---------------------------------------------------------------------------
#define D_MODEL 512
#define NHEAD   8
#define DK      64
#define BATCH   8192
#define SEQ     14
#define MROWS   (BATCH*SEQ)   // 114688

// Scratch (static device globals)
__device__ __half g_Xh  [(size_t)MROWS * D_MODEL];  // X in fp16
__device__ __half g_QKVh[(size_t)MROWS * 1536];     // Q|K|V fused, fp16
__device__ __half g_attnh[(size_t)MROWS * D_MODEL]; // attention out, fp16
__device__ __half g_Wh  [2048 * 512];               // Wq;Wk;Wv;Wo fp16 (row-major over k)
__device__ float  g_bias[2048];                     // bq;bk;bv;bo

// ---------------------------------------------------------------------------
// Helpers
// ---------------------------------------------------------------------------
__device__ __forceinline__ uint32_t smem_u32(const void* p) {
    uint32_t a;
    asm("{ .reg .u64 t; cvta.to.shared.u64 t, %1; cvt.u32.u64 %0, t; }" : "=r"(a) : "l"(p));
    return a;
}
__device__ __forceinline__ void cp16(uint32_t dst, const void* src) {
    asm volatile("cp.async.cg.shared.global [%0], [%1], 16;\n" :: "r"(dst), "l"(src));
}
__device__ __forceinline__ void cp_commit() { asm volatile("cp.async.commit_group;\n" ::: "memory"); }
template <int N> __device__ __forceinline__ void cp_wait() {
    asm volatile("cp.async.wait_group %0;\n" :: "n"(N) : "memory");
}
__device__ __forceinline__ void ldsm_x4(uint32_t r[4], uint32_t addr) {
    asm volatile("ldmatrix.sync.aligned.m8n8.x4.shared.b16 {%0,%1,%2,%3}, [%4];"
                 : "=r"(r[0]), "=r"(r[1]), "=r"(r[2]), "=r"(r[3]) : "r"(addr));
}
__device__ __forceinline__ void mma16816(float c[4], const uint32_t a[4], const uint32_t b[2]) {
    asm volatile(
        "mma.sync.aligned.m16n8k16.row.col.f32.f16.f16.f32 "
        "{%0,%1,%2,%3}, {%4,%5,%6,%7}, {%8,%9}, {%0,%1,%2,%3};\n"
        : "+f"(c[0]), "+f"(c[1]), "+f"(c[2]), "+f"(c[3])
        : "r"(a[0]), "r"(a[1]), "r"(a[2]), "r"(a[3]), "r"(b[0]), "r"(b[1]));
}

// ---------------------------------------------------------------------------
// fp16 multistage GEMM: out[row0+r][bx*128+c] = sum_k A[r][k]*W[wrow0+c][k] + bias
//   A: [MROWS,512] half row-major. W: g_Wh rows (row-major over k) => mma row.col.
//   CTA tile 128x128, BK=32 (2 k16 slabs), 8 warps (warp tile 32x64),
//   4-stage cp.async pipeline, ldmatrix fragment loads.
// ---------------------------------------------------------------------------
#define BM 128
#define BN 128
#define BK 32
#define NSTAGE 4
#define NK (D_MODEL / BK)               // 16
#define ROW_B 80                        // 64B of data + 16B pad (conflict-free ldmatrix)
#define A_ST  (BM * ROW_B)              // 10240
#define B_ST  (BN * ROW_B)              // 10240
#define STAGE (A_ST + B_ST)             // 20480
#define SM_BIAS (NSTAGE * STAGE)        // 81920
#define SM_TOTAL (SM_BIAS + BN * 4)     // 82432

__device__ __forceinline__ void issue_stage(uint32_t sb, int buf, int ks,
                                            const __half* __restrict__ Abase,
                                            const __half* __restrict__ Wbase,
                                            int tid) {
    const uint32_t adst = sb + buf * STAGE;
    const uint32_t bdst = adst + A_ST;
    const int kb = ks * BK;
    #pragma unroll
    for (int t = 0; t < 2; t++) {
        int c = tid + t * 256;           // 0..511
        int r = c >> 2, kc = c & 3;      // row 0..127, 16B chunk 0..3
        cp16(adst + (uint32_t)(r * ROW_B + kc * 16), Abase + (long)r * D_MODEL + kb + kc * 8);
    }
    #pragma unroll
    for (int t = 0; t < 2; t++) {
        int c = tid + t * 256;
        int r = c >> 2, kc = c & 3;
        cp16(bdst + (uint32_t)(r * ROW_B + kc * 16), Wbase + (long)r * D_MODEL + kb + kc * 8);
    }
}

template <typename OutT>
__global__ __launch_bounds__(256, 2)
void gemm_fp16(const __half* __restrict__ A, const __half* __restrict__ W,
               const float* __restrict__ bias, OutT* __restrict__ out,
               int ldo, int wbase)
{
    extern __shared__ char smem[];
    const uint32_t sb = smem_u32(smem);
    float* sBias = (float*)(smem + SM_BIAS);

    const int tid = threadIdx.x;
    const int wid = tid >> 5, lane = tid & 31;
    const int wm = wid >> 1, wn = wid & 1;       // warp tile: rows wm*32, cols wn*64
    const int bx = blockIdx.x, by = blockIdx.y;
    const long row0  = (long)by * BM;
    const int  wrow0 = wbase + bx * BN;

    if (tid < BN) sBias[tid] = bias[wrow0 + tid];

    const __half* Abase = A + row0 * D_MODEL;
    const __half* Wbase = W + (long)wrow0 * D_MODEL;

    float acc[2][8][4];
    #pragma unroll
    for (int i = 0; i < 2; i++)
        #pragma unroll
        for (int j = 0; j < 8; j++)
            #pragma unroll
            for (int k = 0; k < 4; k++) acc[i][j][k] = 0.f;

    // per-lane ldmatrix offsets (within a stage)
    const int sub = lane >> 3, l7 = lane & 7;
    // A: lanes 0-7: rows+0..7 klo | 8-15: rows+8..15 klo | 16-23: rows+0..7 khi | 24-31: rows+8..15 khi
    const uint32_t a_off = (uint32_t)((wm * 32 + (sub & 1) * 8 + l7) * ROW_B + (sub >> 1) * 16);
    // B: lanes 0-7: n+0..7 klo | 8-15: n+0..7 khi | 16-23: n+8..15 klo | 24-31: n+8..15 khi
    const uint32_t b_off = (uint32_t)((wn * 64 + (sub >> 1) * 8 + l7) * ROW_B + (sub & 1) * 16);

    // prologue: stages 0..2
    #pragma unroll
    for (int s = 0; s < NSTAGE - 1; s++) { issue_stage(sb, s, s, Abase, Wbase, tid); cp_commit(); }

    for (int ks = 0; ks < NK; ks++) {
        const int buf = ks & (NSTAGE - 1);
        cp_wait<NSTAGE - 2>();
        __syncthreads();

        // prefetch stage ks+3 into buf (ks-1)%4 (consumed at iter ks-1, safe after this sync)
        const int pf = ks + NSTAGE - 1;
        if (pf < NK) issue_stage(sb, pf & (NSTAGE - 1), pf, Abase, Wbase, tid);
        cp_commit();

        const uint32_t abase = sb + buf * STAGE;
        const uint32_t bbase = abase + A_ST;
        #pragma unroll
        for (int slab = 0; slab < 2; slab++) {      // two k16 slabs per stage
            const uint32_t koff = (uint32_t)(slab * 32);   // 16 halves = 32B
            uint32_t afr[2][4], bfr[8][2];
            #pragma unroll
            for (int mt = 0; mt < 2; mt++)
                ldsm_x4(afr[mt], abase + a_off + (uint32_t)(mt * 16 * ROW_B) + koff);
            #pragma unroll
            for (int ntp = 0; ntp < 4; ntp++) {
                uint32_t r4[4];
                ldsm_x4(r4, bbase + b_off + (uint32_t)(ntp * 16 * ROW_B) + koff);
                bfr[2 * ntp][0] = r4[0]; bfr[2 * ntp][1] = r4[1];
                bfr[2 * ntp + 1][0] = r4[2]; bfr[2 * ntp + 1][1] = r4[3];
            }
            #pragma unroll
            for (int mt = 0; mt < 2; mt++)
                #pragma unroll
                for (int nt = 0; nt < 8; nt++)
                    mma16816(acc[mt][nt], afr[mt], bfr[nt]);
        }
    }

    // epilogue: bias + store
    const int rl = lane >> 2, cl = 2 * (lane & 3);
    #pragma unroll
    for (int mt = 0; mt < 2; mt++) {
        const long r = row0 + wm * 32 + mt * 16 + rl;
        #pragma unroll
        for (int nt = 0; nt < 8; nt++) {
            const int c = wn * 64 + nt * 8 + cl;            // col in 128-tile
            const long cg = (long)bx * BN + c;              // global col
            const float b0 = sBias[c], b1 = sBias[c + 1];
            if constexpr (sizeof(OutT) == 2) {
                __half2* p0 = (__half2*)((__half*)out + r * ldo + cg);
                __half2* p1 = (__half2*)((__half*)out + (r + 8) * ldo + cg);
                *p0 = __float22half2_rn(make_float2(acc[mt][nt][0] + b0, acc[mt][nt][1] + b1));
                *p1 = __float22half2_rn(make_float2(acc[mt][nt][2] + b0, acc[mt][nt][3] + b1));
            } else {
                float* o = (float*)out;
                *(float2*)&o[r * ldo + cg] =
                    make_float2(acc[mt][nt][0] + b0, acc[mt][nt][1] + b1);
                *(float2*)&o[(r + 8) * ldo + cg] =
                    make_float2(acc[mt][nt][2] + b0, acc[mt][nt][3] + b1);
            }
        }
    }
}

// ---------------------------------------------------------------------------
// Attention: one block/batch, one warp/head. fp16 QKV in, fp16 out, f32 math.
// ---------------------------------------------------------------------------
__global__ __launch_bounds__(256, 3)
void attn_kernel(const float* __restrict__ dist,
                 const float* __restrict__ scaleP,
                 const float* __restrict__ powerP)
{
    __shared__ float sPrior[SEQ * SEQ];
    __shared__ float sS[NHEAD][SEQ][SEQ + 1];

    const int tid = threadIdx.x, lane = tid & 31, h = tid >> 5;
    const int b = blockIdx.x;

    if (tid < SEQ * SEQ) {
        float d  = dist[tid];
        float p  = powerP[0];
        float sc = scaleP[0];
        float dp = (d > 0.f) ? expf(p * logf(d)) : 0.f;
        sPrior[tid] = sc / (1.f + dp) * 0.125f;   // fold in 1/sqrt(64)
    }
    __syncthreads();

    const __half* base = g_QKVh + (size_t)b * (SEQ * 1536);
    const int col = h * DK + 2 * lane;

    float2 k[SEQ];
    #pragma unroll
    for (int m = 0; m < SEQ; m++)
        k[m] = __half22float2(*(const __half2*)&base[m * 1536 + 512 + col]);

    #pragma unroll
    for (int n = 0; n < SEQ; n++) {
        float2 qn = __half22float2(*(const __half2*)&base[n * 1536 + col]);
        #pragma unroll
        for (int m = 0; m < SEQ; m++) {
            float v = qn.x * k[m].x + qn.y * k[m].y;
            v += __shfl_xor_sync(0xffffffffu, v, 16);
            v += __shfl_xor_sync(0xffffffffu, v, 8);
            v += __shfl_xor_sync(0xffffffffu, v, 4);
            v += __shfl_xor_sync(0xffffffffu, v, 2);
            v += __shfl_xor_sync(0xffffffffu, v, 1);
            if (lane == m) sS[h][n][m] = v * sPrior[n * SEQ + m];
        }
    }
    __syncwarp();

    if (lane < SEQ) {
        const int n = lane;
        float mx = -1e30f;
        #pragma unroll
        for (int m = 0; m < SEQ; m++) mx = fmaxf(mx, sS[h][n][m]);
        float e[SEQ], sum = 0.f;
        #pragma unroll
        for (int m = 0; m < SEQ; m++) { e[m] = expf(sS[h][n][m] - mx); sum += e[m]; }
        float inv = 1.f / sum;
        #pragma unroll
        for (int m = 0; m < SEQ; m++) sS[h][n][m] = e[m] * inv;
    }
    __syncwarp();

    float2 acc[SEQ];
    #pragma unroll
    for (int n = 0; n < SEQ; n++) acc[n] = make_float2(0.f, 0.f);
    #pragma unroll
    for (int m = 0; m < SEQ; m++) {
        float2 vm = __half22float2(*(const __half2*)&base[m * 1536 + 1024 + col]);
        #pragma unroll
        for (int n = 0; n < SEQ; n++) {
            float a = sS[h][n][m];
            acc[n].x += a * vm.x;
            acc[n].y += a * vm.y;
        }
    }

    __half* outb = g_attnh + (size_t)b * (SEQ * 512);
    #pragma unroll
    for (int n = 0; n < SEQ; n++)
        *(__half2*)&outb[n * 512 + col] = __float22half2_rn(acc[n]);
}

// ---------------------------------------------------------------------------
// Conversions
// ---------------------------------------------------------------------------
__global__ void conv_x_kernel(const float* __restrict__ x, __half* __restrict__ o, long n4) {
    long i = (long)blockIdx.x * blockDim.x + threadIdx.x;
    const long stride = (long)gridDim.x * blockDim.x;
    const float4* xi = (const float4*)x;
    for (; i < n4; i += stride) {
        float4 v = xi[i];
        __half2 lo = __float22half2_rn(make_float2(v.x, v.y));
        __half2 hi = __float22half2_rn(make_float2(v.z, v.w));
        *(uint2*)(o + i * 4) = make_uint2(*(uint32_t*)&lo, *(uint32_t*)&hi);
    }
}

__global__ void conv_w_kernel(const float* __restrict__ Wq, const float* __restrict__ Wk,
                              const float* __restrict__ Wv, const float* __restrict__ Wo,
                              const float* __restrict__ bq, const float* __restrict__ bk,
                              const float* __restrict__ bv, const float* __restrict__ bo,
                              __half* __restrict__ Wc, float* __restrict__ bias) {
    int i = blockIdx.x * 256 + threadIdx.x;
    if (i < 2048 * 512) {
        int r = i >> 9, c = i & 511;
        const float* src = (r < 512) ? Wq : (r < 1024) ? Wk : (r < 1536) ? Wv : Wo;
        Wc[i] = __float2half_rn(src[(r & 511) * 512 + c]);
    }
    if (i < 2048) {
        const float* bs = (i < 512) ? bq : (i < 1024) ? bk : (i < 1536) ? bv : bo;
        bias[i] = bs[i & 511];
    }
}

// ---------------------------------------------------------------------------
// Launch
// ---------------------------------------------------------------------------
extern "C" void kernel_launch(void* const* d_in, const int* in_sizes, int n_in,
                              void* d_out, int out_size)
{
    const float* x     = (const float*)d_in[0];
    const float* Wq    = (const float*)d_in[1];
    const float* bq    = (const float*)d_in[2];
    const float* Wk    = (const float*)d_in[3];
    const float* bk    = (const float*)d_in[4];
    const float* Wv    = (const float*)d_in[5];
    const float* bv    = (const float*)d_in[6];
    const float* Wo    = (const float*)d_in[7];
    const float* bo    = (const float*)d_in[8];
    const float* scale = (const float*)d_in[9];
    const float* power = (const float*)d_in[10];
    const float* dist  = (const float*)d_in[11];
    float* out = (float*)d_out;

    __half *Xh = nullptr, *qkvh = nullptr, *attnh = nullptr, *Wh = nullptr;
    float *bias = nullptr;
    cudaGetSymbolAddress((void**)&Xh,    g_Xh);
    cudaGetSymbolAddress((void**)&qkvh,  g_QKVh);
    cudaGetSymbolAddress((void**)&attnh, g_attnh);
    cudaGetSymbolAddress((void**)&Wh,    g_Wh);
    cudaGetSymbolAddress((void**)&bias,  g_bias);

    cudaFuncSetAttribute(gemm_fp16<__half>, cudaFuncAttributeMaxDynamicSharedMemorySize, SM_TOTAL);
    cudaFuncSetAttribute(gemm_fp16<float>,  cudaFuncAttributeMaxDynamicSharedMemorySize, SM_TOTAL);

    conv_x_kernel<<<4096, 256>>>(x, Xh, (long)MROWS * D_MODEL / 4);
    conv_w_kernel<<<4096, 256>>>(Wq, Wk, Wv, Wo, bq, bk, bv, bo, Wh, bias);

    // QKV projection -> g_QKVh [M x 1536] (half)
    gemm_fp16<__half><<<dim3(12, MROWS / BM), 256, SM_TOTAL>>>(Xh, Wh, bias, qkvh, 1536, 0);

    // Attention per batch item -> g_attnh (half)
    attn_kernel<<<BATCH, 256>>>(dist, scale, power);

    // Output projection -> d_out [M x 512] (f32)
    gemm_fp16<float><<<dim3(4, MROWS / BM), 256, SM_TOTAL>>>(attnh, Wh, bias, out, 512, 1536);
}

// round 4
// speedup vs baseline: 1.7472x; 1.5870x over previous
#include <cuda_runtime.h>
#include <cuda_fp16.h>
#include <cstdint>

// ---------------------------------------------------------------------------
// Problem constants
// ---------------------------------------------------------------------------
#define D_MODEL 512
#define NHEAD   8
#define DK      64
#define BATCH   8192
#define SEQ     14
#define MROWS   (BATCH*SEQ)   // 114688

// Scratch (static device globals)
__device__ __half g_Xh  [(size_t)MROWS * D_MODEL];  // X in fp16
__device__ __half g_QKVh[(size_t)MROWS * 1536];     // Q|K|V fused, fp16
__device__ __half g_attnh[(size_t)MROWS * D_MODEL]; // attention out, fp16
__device__ __half g_Wh  [2048 * 512];               // Wq;Wk;Wv;Wo fp16 (row-major over k)
__device__ float  g_bias[2048];                     // bq;bk;bv;bo

// ---------------------------------------------------------------------------
// Helpers
// ---------------------------------------------------------------------------
__device__ __forceinline__ uint32_t smem_u32(const void* p) {
    uint32_t a;
    asm("{ .reg .u64 t; cvta.to.shared.u64 t, %1; cvt.u32.u64 %0, t; }" : "=r"(a) : "l"(p));
    return a;
}
__device__ __forceinline__ void cp16(uint32_t dst, const void* src) {
    asm volatile("cp.async.cg.shared.global [%0], [%1], 16;\n" :: "r"(dst), "l"(src));
}
__device__ __forceinline__ void cp_commit() { asm volatile("cp.async.commit_group;\n" ::: "memory"); }
template <int N> __device__ __forceinline__ void cp_wait() {
    asm volatile("cp.async.wait_group %0;\n" :: "n"(N) : "memory");
}
__device__ __forceinline__ void ldsm_x4(uint32_t r[4], uint32_t addr) {
    asm volatile("ldmatrix.sync.aligned.m8n8.x4.shared.b16 {%0,%1,%2,%3}, [%4];"
                 : "=r"(r[0]), "=r"(r[1]), "=r"(r[2]), "=r"(r[3]) : "r"(addr));
}
__device__ __forceinline__ void mma16816(float c[4], const uint32_t a[4], const uint32_t b[2]) {
    asm volatile(
        "mma.sync.aligned.m16n8k16.row.col.f32.f16.f16.f32 "
        "{%0,%1,%2,%3}, {%4,%5,%6,%7}, {%8,%9}, {%0,%1,%2,%3};\n"
        : "+f"(c[0]), "+f"(c[1]), "+f"(c[2]), "+f"(c[3])
        : "r"(a[0]), "r"(a[1]), "r"(a[2]), "r"(a[3]), "r"(b[0]), "r"(b[1]));
}

// ---------------------------------------------------------------------------
// fp16 multistage GEMM (unchanged from R3): CTA 128x128, BK=32, 4-stage
// cp.async pipeline, ldmatrix fragments, 8 warps (warp tile 32x64).
// ---------------------------------------------------------------------------
#define BM 128
#define BN 128
#define BK 32
#define NSTAGE 4
#define NK (D_MODEL / BK)               // 16
#define ROW_B 80                        // 64B data + 16B pad (conflict-free ldmatrix)
#define A_ST  (BM * ROW_B)              // 10240
#define B_ST  (BN * ROW_B)              // 10240
#define STAGE (A_ST + B_ST)             // 20480
#define SM_BIAS (NSTAGE * STAGE)        // 81920
#define SM_TOTAL (SM_BIAS + BN * 4)     // 82432

__device__ __forceinline__ void issue_stage(uint32_t sb, int buf, int ks,
                                            const __half* __restrict__ Abase,
                                            const __half* __restrict__ Wbase,
                                            int tid) {
    const uint32_t adst = sb + buf * STAGE;
    const uint32_t bdst = adst + A_ST;
    const int kb = ks * BK;
    #pragma unroll
    for (int t = 0; t < 2; t++) {
        int c = tid + t * 256;           // 0..511
        int r = c >> 2, kc = c & 3;      // row 0..127, 16B chunk 0..3
        cp16(adst + (uint32_t)(r * ROW_B + kc * 16), Abase + (long)r * D_MODEL + kb + kc * 8);
    }
    #pragma unroll
    for (int t = 0; t < 2; t++) {
        int c = tid + t * 256;
        int r = c >> 2, kc = c & 3;
        cp16(bdst + (uint32_t)(r * ROW_B + kc * 16), Wbase + (long)r * D_MODEL + kb + kc * 8);
    }
}

template <typename OutT>
__global__ __launch_bounds__(256, 2)
void gemm_fp16(const __half* __restrict__ A, const __half* __restrict__ W,
               const float* __restrict__ bias, OutT* __restrict__ out,
               int ldo, int wbase)
{
    extern __shared__ char smem[];
    const uint32_t sb = smem_u32(smem);
    float* sBias = (float*)(smem + SM_BIAS);

    const int tid = threadIdx.x;
    const int wid = tid >> 5, lane = tid & 31;
    const int wm = wid >> 1, wn = wid & 1;
    const int bx = blockIdx.x, by = blockIdx.y;
    const long row0  = (long)by * BM;
    const int  wrow0 = wbase + bx * BN;

    if (tid < BN) sBias[tid] = bias[wrow0 + tid];

    const __half* Abase = A + row0 * D_MODEL;
    const __half* Wbase = W + (long)wrow0 * D_MODEL;

    float acc[2][8][4];
    #pragma unroll
    for (int i = 0; i < 2; i++)
        #pragma unroll
        for (int j = 0; j < 8; j++)
            #pragma unroll
            for (int k = 0; k < 4; k++) acc[i][j][k] = 0.f;

    const int sub = lane >> 3, l7 = lane & 7;
    const uint32_t a_off = (uint32_t)((wm * 32 + (sub & 1) * 8 + l7) * ROW_B + (sub >> 1) * 16);
    const uint32_t b_off = (uint32_t)((wn * 64 + (sub >> 1) * 8 + l7) * ROW_B + (sub & 1) * 16);

    #pragma unroll
    for (int s = 0; s < NSTAGE - 1; s++) { issue_stage(sb, s, s, Abase, Wbase, tid); cp_commit(); }

    for (int ks = 0; ks < NK; ks++) {
        const int buf = ks & (NSTAGE - 1);
        cp_wait<NSTAGE - 2>();
        __syncthreads();

        const int pf = ks + NSTAGE - 1;
        if (pf < NK) issue_stage(sb, pf & (NSTAGE - 1), pf, Abase, Wbase, tid);
        cp_commit();

        const uint32_t abase = sb + buf * STAGE;
        const uint32_t bbase = abase + A_ST;
        #pragma unroll
        for (int slab = 0; slab < 2; slab++) {
            const uint32_t koff = (uint32_t)(slab * 32);
            uint32_t afr[2][4], bfr[8][2];
            #pragma unroll
            for (int mt = 0; mt < 2; mt++)
                ldsm_x4(afr[mt], abase + a_off + (uint32_t)(mt * 16 * ROW_B) + koff);
            #pragma unroll
            for (int ntp = 0; ntp < 4; ntp++) {
                uint32_t r4[4];
                ldsm_x4(r4, bbase + b_off + (uint32_t)(ntp * 16 * ROW_B) + koff);
                bfr[2 * ntp][0] = r4[0]; bfr[2 * ntp][1] = r4[1];
                bfr[2 * ntp + 1][0] = r4[2]; bfr[2 * ntp + 1][1] = r4[3];
            }
            #pragma unroll
            for (int mt = 0; mt < 2; mt++)
                #pragma unroll
                for (int nt = 0; nt < 8; nt++)
                    mma16816(acc[mt][nt], afr[mt], bfr[nt]);
        }
    }

    const int rl = lane >> 2, cl = 2 * (lane & 3);
    #pragma unroll
    for (int mt = 0; mt < 2; mt++) {
        const long r = row0 + wm * 32 + mt * 16 + rl;
        #pragma unroll
        for (int nt = 0; nt < 8; nt++) {
            const int c = wn * 64 + nt * 8 + cl;
            const long cg = (long)bx * BN + c;
            const float b0 = sBias[c], b1 = sBias[c + 1];
            if constexpr (sizeof(OutT) == 2) {
                __half2* p0 = (__half2*)((__half*)out + r * ldo + cg);
                __half2* p1 = (__half2*)((__half*)out + (r + 8) * ldo + cg);
                *p0 = __float22half2_rn(make_float2(acc[mt][nt][0] + b0, acc[mt][nt][1] + b1));
                *p1 = __float22half2_rn(make_float2(acc[mt][nt][2] + b0, acc[mt][nt][3] + b1));
            } else {
                float* o = (float*)out;
                *(float2*)&o[r * ldo + cg] =
                    make_float2(acc[mt][nt][0] + b0, acc[mt][nt][1] + b1);
                *(float2*)&o[(r + 8) * ldo + cg] =
                    make_float2(acc[mt][nt][2] + b0, acc[mt][nt][3] + b1);
            }
        }
    }
}

// ---------------------------------------------------------------------------
// Attention v2 — shuffle-free. Block = batch (256 thr, warp = head).
// QKV tile staged to smem as f32. Lane = (g, n): g = d-half (lane>>4),
// n = query row (lane&15, active n<14). Scores: per-lane partial dots from
// regs(Q) x smem-broadcast K, ONE shfl_xor(16) per m to combine halves.
// Softmax fully lane-local. Out = attn @ V from smem-broadcast V.
// ---------------------------------------------------------------------------
#define ATTN_QKV_F (SEQ * 1536)                     // 21504 floats
#define ATTN_SMEM  ((ATTN_QKV_F + SEQ * SEQ) * 4)   // 86800 B

__global__ __launch_bounds__(256, 2)
void attn_kernel(const float* __restrict__ dist,
                 const float* __restrict__ scaleP,
                 const float* __restrict__ powerP)
{
    extern __shared__ float sm[];
    float* sQKV   = sm;                  // [SEQ][1536]
    float* sPrior = sm + ATTN_QKV_F;     // [SEQ*SEQ]

    const int tid = threadIdx.x, lane = tid & 31, h = tid >> 5;
    const int b = blockIdx.x;

    if (tid < SEQ * SEQ) {
        float d  = dist[tid];
        float p  = powerP[0];
        float sc = scaleP[0];
        float dp = (d > 0.f) ? expf(p * logf(d)) : 0.f;
        sPrior[tid] = sc / (1.f + dp) * 0.125f;     // fold in 1/sqrt(64)
    }

    // Stage QKV (half -> float) cooperatively: 2688 x 16B chunks
    {
        const uint4* src = (const uint4*)(g_QKVh + (size_t)b * ATTN_QKV_F);
        for (int i = tid; i < ATTN_QKV_F / 8; i += 256) {
            uint4 v = src[i];
            float2 f0 = __half22float2(*(__half2*)&v.x);
            float2 f1 = __half22float2(*(__half2*)&v.y);
            float2 f2 = __half22float2(*(__half2*)&v.z);
            float2 f3 = __half22float2(*(__half2*)&v.w);
            *(float4*)&sQKV[i * 8]     = make_float4(f0.x, f0.y, f1.x, f1.y);
            *(float4*)&sQKV[i * 8 + 4] = make_float4(f2.x, f2.y, f3.x, f3.y);
        }
    }
    __syncthreads();

    const int g  = lane >> 4;            // d-half: 0 -> d 0..31, 1 -> d 32..63
    const int n  = lane & 15;            // query row (valid < SEQ)
    const int ne = (n < SEQ) ? n : SEQ - 1;
    const int cb = h * DK + g * 32;      // column base within 512

    // Q row in registers (clamped row for inactive lanes; they run but don't store)
    float q[32];
    {
        const float* qp = sQKV + ne * 1536 + cb;
        #pragma unroll
        for (int d = 0; d < 32; d++) q[d] = qp[d];
    }

    // Partial scores
    float sc[SEQ];
    #pragma unroll
    for (int m = 0; m < SEQ; m++) {
        const float* kp = sQKV + m * 1536 + 512 + cb;
        float a = 0.f;
        #pragma unroll
        for (int d = 0; d < 32; d++) a += q[d] * kp[d];
        sc[m] = a;
    }
    // Combine halves (one shfl per m) and apply prior
    #pragma unroll
    for (int m = 0; m < SEQ; m++) {
        float s = sc[m] + __shfl_xor_sync(0xffffffffu, sc[m], 16);
        sc[m] = s * sPrior[ne * SEQ + m];
    }

    // Lane-local softmax
    float mx = sc[0];
    #pragma unroll
    for (int m = 1; m < SEQ; m++) mx = fmaxf(mx, sc[m]);
    float sum = 0.f;
    #pragma unroll
    for (int m = 0; m < SEQ; m++) { sc[m] = __expf(sc[m] - mx); sum += sc[m]; }
    const float inv = 1.f / sum;

    // Out = attn @ V for this lane's 32 dims
    float acc[32];
    #pragma unroll
    for (int d = 0; d < 32; d++) acc[d] = 0.f;
    #pragma unroll
    for (int m = 0; m < SEQ; m++) {
        const float w = sc[m] * inv;
        const float* vp = sQKV + m * 1536 + 1024 + cb;
        #pragma unroll
        for (int d = 0; d < 32; d++) acc[d] += w * vp[d];
    }

    // Store as half (feeds fp16 GEMM2)
    if (n < SEQ) {
        __half* outp = g_attnh + (size_t)b * (SEQ * 512) + n * 512 + cb;
        #pragma unroll
        for (int j = 0; j < 4; j++) {
            __half2 h0 = __float22half2_rn(make_float2(acc[8 * j + 0], acc[8 * j + 1]));
            __half2 h1 = __float22half2_rn(make_float2(acc[8 * j + 2], acc[8 * j + 3]));
            __half2 h2 = __float22half2_rn(make_float2(acc[8 * j + 4], acc[8 * j + 5]));
            __half2 h3 = __float22half2_rn(make_float2(acc[8 * j + 6], acc[8 * j + 7]));
            uint4 v = make_uint4(*(uint32_t*)&h0, *(uint32_t*)&h1,
                                 *(uint32_t*)&h2, *(uint32_t*)&h3);
            *(uint4*)(outp + 8 * j) = v;
        }
    }
}

// ---------------------------------------------------------------------------
// Conversions
// ---------------------------------------------------------------------------
__global__ void conv_x_kernel(const float* __restrict__ x, __half* __restrict__ o, long n4) {
    long i = (long)blockIdx.x * blockDim.x + threadIdx.x;
    const long stride = (long)gridDim.x * blockDim.x;
    const float4* xi = (const float4*)x;
    for (; i < n4; i += stride) {
        float4 v = xi[i];
        __half2 lo = __float22half2_rn(make_float2(v.x, v.y));
        __half2 hi = __float22half2_rn(make_float2(v.z, v.w));
        *(uint2*)(o + i * 4) = make_uint2(*(uint32_t*)&lo, *(uint32_t*)&hi);
    }
}

__global__ void conv_w_kernel(const float* __restrict__ Wq, const float* __restrict__ Wk,
                              const float* __restrict__ Wv, const float* __restrict__ Wo,
                              const float* __restrict__ bq, const float* __restrict__ bk,
                              const float* __restrict__ bv, const float* __restrict__ bo,
                              __half* __restrict__ Wc, float* __restrict__ bias) {
    int i = blockIdx.x * 256 + threadIdx.x;
    if (i < 2048 * 512) {
        int r = i >> 9, c = i & 511;
        const float* src = (r < 512) ? Wq : (r < 1024) ? Wk : (r < 1536) ? Wv : Wo;
        Wc[i] = __float2half_rn(src[(r & 511) * 512 + c]);
    }
    if (i < 2048) {
        const float* bs = (i < 512) ? bq : (i < 1024) ? bk : (i < 1536) ? bv : bo;
        bias[i] = bs[i & 511];
    }
}

// ---------------------------------------------------------------------------
// Launch
// ---------------------------------------------------------------------------
extern "C" void kernel_launch(void* const* d_in, const int* in_sizes, int n_in,
                              void* d_out, int out_size)
{
    const float* x     = (const float*)d_in[0];
    const float* Wq    = (const float*)d_in[1];
    const float* bq    = (const float*)d_in[2];
    const float* Wk    = (const float*)d_in[3];
    const float* bk    = (const float*)d_in[4];
    const float* Wv    = (const float*)d_in[5];
    const float* bv    = (const float*)d_in[6];
    const float* Wo    = (const float*)d_in[7];
    const float* bo    = (const float*)d_in[8];
    const float* scale = (const float*)d_in[9];
    const float* power = (const float*)d_in[10];
    const float* dist  = (const float*)d_in[11];
    float* out = (float*)d_out;

    __half *Xh = nullptr, *qkvh = nullptr, *attnh = nullptr, *Wh = nullptr;
    float *bias = nullptr;
    cudaGetSymbolAddress((void**)&Xh,    g_Xh);
    cudaGetSymbolAddress((void**)&qkvh,  g_QKVh);
    cudaGetSymbolAddress((void**)&attnh, g_attnh);
    cudaGetSymbolAddress((void**)&Wh,    g_Wh);
    cudaGetSymbolAddress((void**)&bias,  g_bias);

    cudaFuncSetAttribute(gemm_fp16<__half>, cudaFuncAttributeMaxDynamicSharedMemorySize, SM_TOTAL);
    cudaFuncSetAttribute(gemm_fp16<float>,  cudaFuncAttributeMaxDynamicSharedMemorySize, SM_TOTAL);
    cudaFuncSetAttribute(attn_kernel, cudaFuncAttributeMaxDynamicSharedMemorySize, ATTN_SMEM);

    conv_x_kernel<<<4096, 256>>>(x, Xh, (long)MROWS * D_MODEL / 4);
    conv_w_kernel<<<4096, 256>>>(Wq, Wk, Wv, Wo, bq, bk, bv, bo, Wh, bias);

    // QKV projection -> g_QKVh [M x 1536] (half)
    gemm_fp16<__half><<<dim3(12, MROWS / BM), 256, SM_TOTAL>>>(Xh, Wh, bias, qkvh, 1536, 0);

    // Attention per batch item -> g_attnh (half)
    attn_kernel<<<BATCH, 256, ATTN_SMEM>>>(dist, scale, power);

    // Output projection -> d_out [M x 512] (f32)
    gemm_fp16<float><<<dim3(4, MROWS / BM), 256, SM_TOTAL>>>(attnh, Wh, bias, out, 512, 1536);
}

// round 5
// speedup vs baseline: 1.8879x; 1.0805x over previous
#include <cuda_runtime.h>
#include <cuda_fp16.h>
#include <cstdint>

// ---------------------------------------------------------------------------
// Problem constants
// ---------------------------------------------------------------------------
#define D_MODEL 512
#define NHEAD   8
#define DK      64
#define BATCH   8192
#define SEQ     14
#define MROWS   (BATCH*SEQ)   // 114688

// Scratch (static device globals)
__device__ __half g_Xh  [(size_t)MROWS * D_MODEL];  // X in fp16
__device__ __half g_QKVh[(size_t)MROWS * 1536];     // Q|K|V fused, fp16
__device__ __half g_attnh[(size_t)MROWS * D_MODEL]; // attention out, fp16
__device__ __half g_Wh  [2048 * 512];               // Wq;Wk;Wv;Wo fp16 (row-major over k)
__device__ float  g_bias[2048];                     // bq;bk;bv;bo

// ---------------------------------------------------------------------------
// Helpers
// ---------------------------------------------------------------------------
__device__ __forceinline__ uint32_t smem_u32(const void* p) {
    uint32_t a;
    asm("{ .reg .u64 t; cvta.to.shared.u64 t, %1; cvt.u32.u64 %0, t; }" : "=r"(a) : "l"(p));
    return a;
}
__device__ __forceinline__ void cp16(uint32_t dst, const void* src) {
    asm volatile("cp.async.cg.shared.global [%0], [%1], 16;\n" :: "r"(dst), "l"(src));
}
__device__ __forceinline__ void cp_commit() { asm volatile("cp.async.commit_group;\n" ::: "memory"); }
template <int N> __device__ __forceinline__ void cp_wait() {
    asm volatile("cp.async.wait_group %0;\n" :: "n"(N) : "memory");
}
__device__ __forceinline__ void ldsm_x4(uint32_t r[4], uint32_t addr) {
    asm volatile("ldmatrix.sync.aligned.m8n8.x4.shared.b16 {%0,%1,%2,%3}, [%4];"
                 : "=r"(r[0]), "=r"(r[1]), "=r"(r[2]), "=r"(r[3]) : "r"(addr));
}
__device__ __forceinline__ void mma16816(float c[4], const uint32_t a[4], const uint32_t b[2]) {
    asm volatile(
        "mma.sync.aligned.m16n8k16.row.col.f32.f16.f16.f32 "
        "{%0,%1,%2,%3}, {%4,%5,%6,%7}, {%8,%9}, {%0,%1,%2,%3};\n"
        : "+f"(c[0]), "+f"(c[1]), "+f"(c[2]), "+f"(c[3])
        : "r"(a[0]), "r"(a[1]), "r"(a[2]), "r"(a[3]), "r"(b[0]), "r"(b[1]));
}

// ---------------------------------------------------------------------------
// fp16 multistage GEMM: CTA 128x128, BK=32, 4-stage cp.async pipeline,
// 4 warps (warp tile 64x64 — LDSM/HMMA = 0.25), ldmatrix fragments.
// ---------------------------------------------------------------------------
#define BM 128
#define BN 128
#define BK 32
#define NSTAGE 4
#define NK (D_MODEL / BK)               // 16
#define ROW_B 80                        // 64B data + 16B pad (conflict-free ldmatrix)
#define A_ST  (BM * ROW_B)              // 10240
#define B_ST  (BN * ROW_B)              // 10240
#define STAGE (A_ST + B_ST)             // 20480
#define SM_BIAS (NSTAGE * STAGE)        // 81920
#define SM_TOTAL (SM_BIAS + BN * 4)     // 82432
#define GTHREADS 128

__device__ __forceinline__ void issue_stage(uint32_t sb, int buf, int ks,
                                            const __half* __restrict__ Abase,
                                            const __half* __restrict__ Wbase,
                                            int tid) {
    const uint32_t adst = sb + buf * STAGE;
    const uint32_t bdst = adst + A_ST;
    const int kb = ks * BK;
    #pragma unroll
    for (int t = 0; t < 4; t++) {
        int c = tid + t * GTHREADS;      // 0..511
        int r = c >> 2, kc = c & 3;      // row 0..127, 16B chunk 0..3
        cp16(adst + (uint32_t)(r * ROW_B + kc * 16), Abase + (long)r * D_MODEL + kb + kc * 8);
    }
    #pragma unroll
    for (int t = 0; t < 4; t++) {
        int c = tid + t * GTHREADS;
        int r = c >> 2, kc = c & 3;
        cp16(bdst + (uint32_t)(r * ROW_B + kc * 16), Wbase + (long)r * D_MODEL + kb + kc * 8);
    }
}

template <typename OutT>
__global__ __launch_bounds__(GTHREADS, 2)
void gemm_fp16(const __half* __restrict__ A, const __half* __restrict__ W,
               const float* __restrict__ bias, OutT* __restrict__ out,
               int ldo, int wbase)
{
    extern __shared__ char smem[];
    const uint32_t sb = smem_u32(smem);
    float* sBias = (float*)(smem + SM_BIAS);

    const int tid = threadIdx.x;
    const int wid = tid >> 5, lane = tid & 31;
    const int wm = wid >> 1, wn = wid & 1;       // warp tile: rows wm*64, cols wn*64
    const int bx = blockIdx.x, by = blockIdx.y;
    const long row0  = (long)by * BM;
    const int  wrow0 = wbase + bx * BN;

    if (tid < BN) sBias[tid] = bias[wrow0 + tid];

    const __half* Abase = A + row0 * D_MODEL;
    const __half* Wbase = W + (long)wrow0 * D_MODEL;

    float acc[4][8][4];
    #pragma unroll
    for (int i = 0; i < 4; i++)
        #pragma unroll
        for (int j = 0; j < 8; j++)
            #pragma unroll
            for (int k = 0; k < 4; k++) acc[i][j][k] = 0.f;

    const int sub = lane >> 3, l7 = lane & 7;
    // A: lanes 0-7 rows+0..7 klo | 8-15 rows+8..15 klo | 16-23 rows+0..7 khi | 24-31 rows+8..15 khi
    const uint32_t a_off = (uint32_t)((wm * 64 + (sub & 1) * 8 + l7) * ROW_B + (sub >> 1) * 16);
    // B: lanes 0-7 n+0..7 klo | 8-15 n+0..7 khi | 16-23 n+8..15 klo | 24-31 n+8..15 khi
    const uint32_t b_off = (uint32_t)((wn * 64 + (sub >> 1) * 8 + l7) * ROW_B + (sub & 1) * 16);

    #pragma unroll
    for (int s = 0; s < NSTAGE - 1; s++) { issue_stage(sb, s, s, Abase, Wbase, tid); cp_commit(); }

    for (int ks = 0; ks < NK; ks++) {
        const int buf = ks & (NSTAGE - 1);
        cp_wait<NSTAGE - 2>();
        __syncthreads();

        const int pf = ks + NSTAGE - 1;
        if (pf < NK) issue_stage(sb, pf & (NSTAGE - 1), pf, Abase, Wbase, tid);
        cp_commit();

        const uint32_t abase = sb + buf * STAGE;
        const uint32_t bbase = abase + A_ST;
        #pragma unroll
        for (int slab = 0; slab < 2; slab++) {      // two k16 slabs per stage
            const uint32_t koff = (uint32_t)(slab * 32);
            uint32_t afr[4][4], bfr[8][2];
            #pragma unroll
            for (int mt = 0; mt < 4; mt++)
                ldsm_x4(afr[mt], abase + a_off + (uint32_t)(mt * 16 * ROW_B) + koff);
            #pragma unroll
            for (int ntp = 0; ntp < 4; ntp++) {
                uint32_t r4[4];
                ldsm_x4(r4, bbase + b_off + (uint32_t)(ntp * 16 * ROW_B) + koff);
                bfr[2 * ntp][0] = r4[0]; bfr[2 * ntp][1] = r4[1];
                bfr[2 * ntp + 1][0] = r4[2]; bfr[2 * ntp + 1][1] = r4[3];
            }
            #pragma unroll
            for (int mt = 0; mt < 4; mt++)
                #pragma unroll
                for (int nt = 0; nt < 8; nt++)
                    mma16816(acc[mt][nt], afr[mt], bfr[nt]);
        }
    }

    const int rl = lane >> 2, cl = 2 * (lane & 3);
    #pragma unroll
    for (int mt = 0; mt < 4; mt++) {
        const long r = row0 + wm * 64 + mt * 16 + rl;
        #pragma unroll
        for (int nt = 0; nt < 8; nt++) {
            const int c = wn * 64 + nt * 8 + cl;
            const long cg = (long)bx * BN + c;
            const float b0 = sBias[c], b1 = sBias[c + 1];
            if constexpr (sizeof(OutT) == 2) {
                __half2* p0 = (__half2*)((__half*)out + r * ldo + cg);
                __half2* p1 = (__half2*)((__half*)out + (r + 8) * ldo + cg);
                *p0 = __float22half2_rn(make_float2(acc[mt][nt][0] + b0, acc[mt][nt][1] + b1));
                *p1 = __float22half2_rn(make_float2(acc[mt][nt][2] + b0, acc[mt][nt][3] + b1));
            } else {
                float* o = (float*)out;
                *(float2*)&o[r * ldo + cg] =
                    make_float2(acc[mt][nt][0] + b0, acc[mt][nt][1] + b1);
                *(float2*)&o[(r + 8) * ldo + cg] =
                    make_float2(acc[mt][nt][2] + b0, acc[mt][nt][3] + b1);
            }
        }
    }
}

// ---------------------------------------------------------------------------
// Attention v3 — 512 threads/block, 2 warps per head, half smem.
// Lane = (g, n): g = (warp&1)*2 + (lane>>4) selects 16 dims [g*16, g*16+16),
// n = lane&15 = query row (active n<14).
// Scores: 16-dim partial dots (f32 from half smem), shfl_xor(16) -> 32-dim
// partial per warp, cross-warp combine via padded smem buffer.
// Softmax lane-local. Out = attn @ V for the lane's 16 dims.
// ---------------------------------------------------------------------------
#define ATTN_QKV_H  (SEQ * 1536)                        // 21504 halves
#define SPART_OFF   (ATTN_QKV_H * 2)                    // 43008 B
#define SPART_SZ    (NHEAD * 2 * 16 * 17 * 4)           // 17408 B
#define SPRIOR_OFF  (SPART_OFF + SPART_SZ)              // 60416 B
#define ATTN_SMEM   (SPRIOR_OFF + SEQ * SEQ * 4)        // 61200 B

__global__ __launch_bounds__(512, 2)
void attn_kernel(const float* __restrict__ dist,
                 const float* __restrict__ scaleP,
                 const float* __restrict__ powerP)
{
    extern __shared__ char asm_[];
    __half* sQKV   = (__half*)asm_;                     // [SEQ][1536] halves
    float*  sPart  = (float*)(asm_ + SPART_OFF);        // [8][2][16][17]
    float*  sPrior = (float*)(asm_ + SPRIOR_OFF);       // [SEQ*SEQ]

    const int tid = threadIdx.x, lane = tid & 31, wid = tid >> 5;
    const int h = wid >> 1, w = wid & 1;
    const int b = blockIdx.x;

    if (tid < SEQ * SEQ) {
        float d  = dist[tid];
        float p  = powerP[0];
        float sc = scaleP[0];
        float dp = (d > 0.f) ? expf(p * logf(d)) : 0.f;
        sPrior[tid] = sc / (1.f + dp) * 0.125f;         // fold in 1/sqrt(64)
    }

    // Stage QKV raw (half): 2688 uint4 chunks, coalesced
    {
        const uint4* src = (const uint4*)(g_QKVh + (size_t)b * ATTN_QKV_H);
        uint4* dst = (uint4*)sQKV;
        for (int i = tid; i < ATTN_QKV_H / 8; i += 512) dst[i] = src[i];
    }
    __syncthreads();

    const int gq = w * 2 + (lane >> 4);   // dim quarter 0..3
    const int n  = lane & 15;             // query row (valid < SEQ)
    const int ne = (n < SEQ) ? n : SEQ - 1;
    const int cb = h * DK + gq * 16;      // column base within 512 (halves)

    // Q segment (16 dims) -> f32 regs
    float q[16];
    {
        const uint4* qp = (const uint4*)(sQKV + ne * 1536 + cb);
        uint4 v0 = qp[0], v1 = qp[1];
        const __half2* hp0 = (const __half2*)&v0;
        const __half2* hp1 = (const __half2*)&v1;
        #pragma unroll
        for (int j = 0; j < 4; j++) {
            float2 f = __half22float2(hp0[j]);
            q[2 * j] = f.x; q[2 * j + 1] = f.y;
            float2 g2 = __half22float2(hp1[j]);
            q[8 + 2 * j] = g2.x; q[8 + 2 * j + 1] = g2.y;
        }
    }

    // Partial scores over this lane's 16 dims
    float sc[SEQ];
    #pragma unroll
    for (int m = 0; m < SEQ; m++) {
        const uint4* kp = (const uint4*)(sQKV + m * 1536 + 512 + cb);
        uint4 v0 = kp[0], v1 = kp[1];
        const __half2* hp0 = (const __half2*)&v0;
        const __half2* hp1 = (const __half2*)&v1;
        float a = 0.f;
        #pragma unroll
        for (int j = 0; j < 4; j++) {
            float2 f = __half22float2(hp0[j]);
            a += q[2 * j] * f.x + q[2 * j + 1] * f.y;
            float2 g2 = __half22float2(hp1[j]);
            a += q[8 + 2 * j] * g2.x + q[8 + 2 * j + 1] * g2.y;
        }
        sc[m] = a;
    }
    // Combine the warp's two 16-dim quarters -> 32-dim partial
    #pragma unroll
    for (int m = 0; m < SEQ; m++)
        sc[m] += __shfl_xor_sync(0xffffffffu, sc[m], 16);

    // Cross-warp exchange: warp w holds dims [w*32, w*32+32)
    float* myPart = sPart + ((h * 2 + w) * 16 + n) * 17;
    if (lane < 16) {
        #pragma unroll
        for (int m = 0; m < SEQ; m++) myPart[m] = sc[m];
    }
    __syncthreads();

    {
        const float* p0 = sPart + ((h * 2 + 0) * 16 + n) * 17;
        const float* p1 = sPart + ((h * 2 + 1) * 16 + n) * 17;
        const float* pr = sPrior + ne * SEQ;
        #pragma unroll
        for (int m = 0; m < SEQ; m++)
            sc[m] = (p0[m] + p1[m]) * pr[m];
    }

    // Lane-local softmax
    float mx = sc[0];
    #pragma unroll
    for (int m = 1; m < SEQ; m++) mx = fmaxf(mx, sc[m]);
    float sum = 0.f;
    #pragma unroll
    for (int m = 0; m < SEQ; m++) { sc[m] = __expf(sc[m] - mx); sum += sc[m]; }
    const float inv = 1.f / sum;

    // Out = attn @ V for this lane's 16 dims
    float acc[16];
    #pragma unroll
    for (int d = 0; d < 16; d++) acc[d] = 0.f;
    #pragma unroll
    for (int m = 0; m < SEQ; m++) {
        const float wgt = sc[m] * inv;
        const uint4* vp = (const uint4*)(sQKV + m * 1536 + 1024 + cb);
        uint4 v0 = vp[0], v1 = vp[1];
        const __half2* hp0 = (const __half2*)&v0;
        const __half2* hp1 = (const __half2*)&v1;
        #pragma unroll
        for (int j = 0; j < 4; j++) {
            float2 f = __half22float2(hp0[j]);
            acc[2 * j]     += wgt * f.x;
            acc[2 * j + 1] += wgt * f.y;
            float2 g2 = __half22float2(hp1[j]);
            acc[8 + 2 * j]     += wgt * g2.x;
            acc[8 + 2 * j + 1] += wgt * g2.y;
        }
    }

    // Store 16 halves (feeds fp16 GEMM2)
    if (n < SEQ) {
        __half* outp = g_attnh + (size_t)b * (SEQ * 512) + n * 512 + cb;
        uint4 v0, v1;
        __half2* o0 = (__half2*)&v0;
        __half2* o1 = (__half2*)&v1;
        #pragma unroll
        for (int j = 0; j < 4; j++) {
            o0[j] = __float22half2_rn(make_float2(acc[2 * j], acc[2 * j + 1]));
            o1[j] = __float22half2_rn(make_float2(acc[8 + 2 * j], acc[8 + 2 * j + 1]));
        }
        ((uint4*)outp)[0] = v0;
        ((uint4*)outp)[1] = v1;
    }
}

// ---------------------------------------------------------------------------
// Conversions
// ---------------------------------------------------------------------------
__global__ void conv_x_kernel(const float* __restrict__ x, __half* __restrict__ o, long n4) {
    long i = (long)blockIdx.x * blockDim.x + threadIdx.x;
    const long stride = (long)gridDim.x * blockDim.x;
    const float4* xi = (const float4*)x;
    for (; i < n4; i += stride) {
        float4 v = xi[i];
        __half2 lo = __float22half2_rn(make_float2(v.x, v.y));
        __half2 hi = __float22half2_rn(make_float2(v.z, v.w));
        *(uint2*)(o + i * 4) = make_uint2(*(uint32_t*)&lo, *(uint32_t*)&hi);
    }
}

__global__ void conv_w_kernel(const float* __restrict__ Wq, const float* __restrict__ Wk,
                              const float* __restrict__ Wv, const float* __restrict__ Wo,
                              const float* __restrict__ bq, const float* __restrict__ bk,
                              const float* __restrict__ bv, const float* __restrict__ bo,
                              __half* __restrict__ Wc, float* __restrict__ bias) {
    int i = blockIdx.x * 256 + threadIdx.x;
    if (i < 2048 * 512) {
        int r = i >> 9, c = i & 511;
        const float* src = (r < 512) ? Wq : (r < 1024) ? Wk : (r < 1536) ? Wv : Wo;
        Wc[i] = __float2half_rn(src[(r & 511) * 512 + c]);
    }
    if (i < 2048) {
        const float* bs = (i < 512) ? bq : (i < 1024) ? bk : (i < 1536) ? bv : bo;
        bias[i] = bs[i & 511];
    }
}

// ---------------------------------------------------------------------------
// Launch
// ---------------------------------------------------------------------------
extern "C" void kernel_launch(void* const* d_in, const int* in_sizes, int n_in,
                              void* d_out, int out_size)
{
    const float* x     = (const float*)d_in[0];
    const float* Wq    = (const float*)d_in[1];
    const float* bq    = (const float*)d_in[2];
    const float* Wk    = (const float*)d_in[3];
    const float* bk    = (const float*)d_in[4];
    const float* Wv    = (const float*)d_in[5];
    const float* bv    = (const float*)d_in[6];
    const float* Wo    = (const float*)d_in[7];
    const float* bo    = (const float*)d_in[8];
    const float* scale = (const float*)d_in[9];
    const float* power = (const float*)d_in[10];
    const float* dist  = (const float*)d_in[11];
    float* out = (float*)d_out;

    __half *Xh = nullptr, *qkvh = nullptr, *attnh = nullptr, *Wh = nullptr;
    float *bias = nullptr;
    cudaGetSymbolAddress((void**)&Xh,    g_Xh);
    cudaGetSymbolAddress((void**)&qkvh,  g_QKVh);
    cudaGetSymbolAddress((void**)&attnh, g_attnh);
    cudaGetSymbolAddress((void**)&Wh,    g_Wh);
    cudaGetSymbolAddress((void**)&bias,  g_bias);

    cudaFuncSetAttribute(gemm_fp16<__half>, cudaFuncAttributeMaxDynamicSharedMemorySize, SM_TOTAL);
    cudaFuncSetAttribute(gemm_fp16<float>,  cudaFuncAttributeMaxDynamicSharedMemorySize, SM_TOTAL);
    cudaFuncSetAttribute(attn_kernel, cudaFuncAttributeMaxDynamicSharedMemorySize, ATTN_SMEM);

    conv_x_kernel<<<4096, 256>>>(x, Xh, (long)MROWS * D_MODEL / 4);
    conv_w_kernel<<<4096, 256>>>(Wq, Wk, Wv, Wo, bq, bk, bv, bo, Wh, bias);

    // QKV projection -> g_QKVh [M x 1536] (half)
    gemm_fp16<__half><<<dim3(12, MROWS / BM), GTHREADS, SM_TOTAL>>>(Xh, Wh, bias, qkvh, 1536, 0);

    // Attention per batch item -> g_attnh (half)
    attn_kernel<<<BATCH, 512, ATTN_SMEM>>>(dist, scale, power);

    // Output projection -> d_out [M x 512] (f32)
    gemm_fp16<float><<<dim3(4, MROWS / BM), GTHREADS, SM_TOTAL>>>(attnh, Wh, bias, out, 512, 1536);
}